// round 3
// baseline (speedup 1.0000x reference)
#include <cuda_runtime.h>
#include <math.h>
#include <stdint.h>

// Problem constants
#define BB 2
#define LL 1024
#define EE 1024
#define HH 16
#define DD 64
#define NCH 16          // chunks per (b,h)
#define CHK 64          // chunk length
#define ST_STRIDE 8320  // per-chunk state: Sc(4096) Ss(4096) Zc(64) Zs(64)
#define ROWS (BB*LL)    // 2048

// GEMM pipeline config
#define STAGES 3
#define APITCH 36       // A smem row pitch (floats), [m][k]
#define BPITCH 132      // B smem row pitch (floats), [k][n]
#define STAGE_FLOATS (128 * APITCH + 32 * BPITCH)   // 4608 + 4224 = 8832
#define GEMM_SMEM_BYTES (STAGES * STAGE_FLOATS * 4) // 105984

// Scratch (device globals; no allocs allowed)
__device__ float g_xn[ROWS * EE];        // 8 MB
__device__ float g_qkv[ROWS * 3 * EE];   // 24 MB
__device__ float g_attn[ROWS * EE];      // 8 MB
__device__ float g_h[ROWS * EE];         // 8 MB
__device__ float g_mid[ROWS * 4 * EE];   // 32 MB
__device__ float g_state[BB * HH * NCH * ST_STRIDE]; // ~17 MB

// ---------------------------------------------------------------------------
// RMSNorm: one block per row (E=1024), 256 threads, 1 float4 each
// ---------------------------------------------------------------------------
__global__ void rmsnorm_kernel(const float* __restrict__ x,
                               const float* __restrict__ w,
                               float* __restrict__ out) {
    int row = blockIdx.x;
    int tid = threadIdx.x;
    const float4* xr = (const float4*)(x + (size_t)row * EE);
    float4 v = xr[tid];
    float ss = v.x*v.x + v.y*v.y + v.z*v.z + v.w*v.w;
    #pragma unroll
    for (int o = 16; o; o >>= 1) ss += __shfl_xor_sync(0xffffffffu, ss, o);
    __shared__ float red[8];
    if ((tid & 31) == 0) red[tid >> 5] = ss;
    __syncthreads();
    float tot = 0.f;
    #pragma unroll
    for (int i = 0; i < 8; i++) tot += red[i];
    float scale = rsqrtf(tot * (1.0f / (float)EE) + 1e-6f);
    float4 wv = ((const float4*)w)[tid];
    float4 o;
    o.x = v.x * scale * wv.x;
    o.y = v.y * scale * wv.y;
    o.z = v.z * scale * wv.z;
    o.w = v.w * scale * wv.w;
    ((float4*)(out + (size_t)row * EE))[tid] = o;
}

// ---------------------------------------------------------------------------
// TF32 tensor-core GEMM with 3-stage cp.async pipeline.
// C[M,N] = A[M,K] @ W[K,N] + bias (+GELU | +residual)
// 128x128 tile, BK=32, 256 threads = 8 warps (2x4), warp tile 64x32,
// mma.sync.m16n8k8.tf32, fp32 accumulate, cvt-to-tf32 in registers.
// epi: 0 = bias, 1 = bias+gelu(tanh), 2 = bias+residual
// ---------------------------------------------------------------------------
__device__ __forceinline__ uint32_t f2tf32(float f) {
    uint32_t r;
    asm("cvt.rna.tf32.f32 %0, %1;" : "=r"(r) : "f"(f));
    return r;
}

__device__ __forceinline__ void mma_tf32(float* c, const uint32_t* a, const uint32_t* b) {
    asm volatile(
        "mma.sync.aligned.m16n8k8.row.col.f32.tf32.tf32.f32 "
        "{%0,%1,%2,%3}, {%4,%5,%6,%7}, {%8,%9}, {%0,%1,%2,%3};"
        : "+f"(c[0]), "+f"(c[1]), "+f"(c[2]), "+f"(c[3])
        : "r"(a[0]), "r"(a[1]), "r"(a[2]), "r"(a[3]),
          "r"(b[0]), "r"(b[1]));
}

__device__ __forceinline__ void cpasync16(float* smem_ptr, const float* gptr) {
    uint32_t s = (uint32_t)__cvta_generic_to_shared(smem_ptr);
    asm volatile("cp.async.cg.shared.global [%0], [%1], 16;\n" :: "r"(s), "l"(gptr));
}
__device__ __forceinline__ void cpasync_commit() {
    asm volatile("cp.async.commit_group;\n" ::: "memory");
}
template <int N>
__device__ __forceinline__ void cpasync_wait() {
    asm volatile("cp.async.wait_group %0;\n" :: "n"(N) : "memory");
}

__global__ void __launch_bounds__(256)
tgemm_kernel(const float* __restrict__ A, const float* __restrict__ W,
             const float* __restrict__ bias, const float* __restrict__ res,
             float* __restrict__ C, int M, int N, int K, int epi) {
    extern __shared__ float sm[];

    int tid = threadIdx.x;
    int bx = blockIdx.x;   // N tile
    int by = blockIdx.y;   // M tile
    int warp = tid >> 5;
    int lane = tid & 31;
    int wm = warp >> 2;    // 0..1  (M dir, 64 rows each)
    int wn = warp & 3;     // 0..3  (N dir, 32 cols each)
    int g  = lane >> 2;    // 0..7
    int tg = lane & 3;     // 0..3

    float acc[4][4][4];
    #pragma unroll
    for (int mi = 0; mi < 4; mi++)
        #pragma unroll
        for (int ni = 0; ni < 4; ni++)
            #pragma unroll
            for (int r = 0; r < 4; r++) acc[mi][ni][r] = 0.f;

    // Global copy mapping (per-thread: 4x16B for A, 4x16B for B per tile)
    int arow = tid >> 1;           // 0..127
    int acol = (tid & 1) * 16;     // 0 or 16
    const float* Ag = A + (size_t)(by * 128 + arow) * K + acol;
    int brow = tid >> 3;           // 0..31
    int bcol = (tid & 7) * 16;     // 0..112
    const float* Wg = W + (size_t)brow * N + bx * 128 + bcol;

    int nT = K >> 5;

    // issue a stage copy: tile index t -> buffer t % STAGES
    auto issue = [&](int t) {
        float* sA = sm + (t % STAGES) * STAGE_FLOATS;
        float* sB = sA + 128 * APITCH;
        const float* Asrc = Ag + t * 32;
        const float* Bsrc = Wg + (size_t)t * 32 * N;
        #pragma unroll
        for (int i = 0; i < 4; i++)
            cpasync16(sA + arow * APITCH + acol + i * 4, Asrc + i * 4);
        #pragma unroll
        for (int i = 0; i < 4; i++)
            cpasync16(sB + brow * BPITCH + bcol + i * 4, Bsrc + i * 4);
    };

    // prologue: stages 0..STAGES-2
    #pragma unroll
    for (int s = 0; s < STAGES - 1; s++) {
        issue(s);
        cpasync_commit();
    }

    int m0base = wm * 64;
    int n0base = wn * 32;

    for (int t = 0; t < nT; t++) {
        cpasync_wait<STAGES - 2>();   // tile t resident
        __syncthreads();              // also retires all reads of tile t-1

        if (t + STAGES - 1 < nT) issue(t + STAGES - 1);
        cpasync_commit();

        const float* sA = sm + (t % STAGES) * STAGE_FLOATS;
        const float* sB = sA + 128 * APITCH;

        #pragma unroll
        for (int ks = 0; ks < 4; ks++) {
            int k0 = ks * 8;
            uint32_t af[4][4];
            #pragma unroll
            for (int mi = 0; mi < 4; mi++) {
                int m0 = m0base + mi * 16;
                af[mi][0] = f2tf32(sA[(m0 + g) * APITCH + k0 + tg]);
                af[mi][1] = f2tf32(sA[(m0 + g + 8) * APITCH + k0 + tg]);
                af[mi][2] = f2tf32(sA[(m0 + g) * APITCH + k0 + tg + 4]);
                af[mi][3] = f2tf32(sA[(m0 + g + 8) * APITCH + k0 + tg + 4]);
            }
            uint32_t bf[4][2];
            #pragma unroll
            for (int ni = 0; ni < 4; ni++) {
                int n0 = n0base + ni * 8;
                bf[ni][0] = f2tf32(sB[(k0 + tg) * BPITCH + n0 + g]);
                bf[ni][1] = f2tf32(sB[(k0 + tg + 4) * BPITCH + n0 + g]);
            }
            #pragma unroll
            for (int mi = 0; mi < 4; mi++)
                #pragma unroll
                for (int ni = 0; ni < 4; ni++)
                    mma_tf32(acc[mi][ni], af[mi], bf[ni]);
        }
    }

    // Epilogue. c0:(g, 2tg) c1:(g, 2tg+1) c2:(g+8, 2tg) c3:(g+8, 2tg+1)
    #pragma unroll
    for (int mi = 0; mi < 4; mi++) {
        #pragma unroll
        for (int ni = 0; ni < 4; ni++) {
            int col = bx * 128 + wn * 32 + ni * 8 + tg * 2;
            float b0 = bias[col], b1 = bias[col + 1];
            #pragma unroll
            for (int half = 0; half < 2; half++) {
                int row = by * 128 + wm * 64 + mi * 16 + g + half * 8;
                size_t off = (size_t)row * N + col;
                float v0 = acc[mi][ni][half * 2 + 0] + b0;
                float v1 = acc[mi][ni][half * 2 + 1] + b1;
                if (epi == 1) {
                    float u0 = v0 * (0.7978845608028654f + 0.035677408136300125f * v0 * v0);
                    float u1 = v1 * (0.7978845608028654f + 0.035677408136300125f * v1 * v1);
                    v0 = 0.5f * v0 * (1.f + tanhf(u0));
                    v1 = 0.5f * v1 * (1.f + tanhf(u1));
                } else if (epi == 2) {
                    v0 += res[off];
                    v1 += res[off + 1];
                }
                *(float2*)(C + off) = make_float2(v0, v1);
            }
        }
    }
}

// ---------------------------------------------------------------------------
// Attention pass A: per-chunk state sums.
// ---------------------------------------------------------------------------
__global__ void __launch_bounds__(256)
attn_chunk_state(const float* __restrict__ qkv, float* __restrict__ state) {
    int blk = blockIdx.x;
    int c = blk % NCH;
    int bh = blk / NCH;
    int b = bh / HH, h = bh % HH;

    __shared__ float sk[CHK][DD + 1];
    __shared__ float sv[CHK][DD + 1];
    __shared__ float cw[CHK], sw[CHK];

    int tid = threadIdx.x;
    for (int idx = tid; idx < CHK * 16; idx += 256) {
        int j = idx >> 4;
        int dd = (idx & 15) << 2;
        int l = c * CHK + j;
        const float* base = qkv + (size_t)(b * LL + l) * (3 * EE) + h * DD;
        float4 kv = *(const float4*)(base + EE + dd);
        float4 vv = *(const float4*)(base + 2 * EE + dd);
        sk[j][dd + 0] = fmaxf(kv.x, 0.f);
        sk[j][dd + 1] = fmaxf(kv.y, 0.f);
        sk[j][dd + 2] = fmaxf(kv.z, 0.f);
        sk[j][dd + 3] = fmaxf(kv.w, 0.f);
        sv[j][dd + 0] = vv.x;
        sv[j][dd + 1] = vv.y;
        sv[j][dd + 2] = vv.z;
        sv[j][dd + 3] = vv.w;
    }
    if (tid < CHK) {
        float ang = 1.5707963267948966f * (float)(c * CHK + tid) / (float)LL;
        cw[tid] = cosf(ang);
        sw[tid] = sinf(ang);
    }
    __syncthreads();

    int e  = tid & 63;
    int d0 = (tid >> 6) * 16;
    float accC[16], accS[16];
    #pragma unroll
    for (int r = 0; r < 16; r++) { accC[r] = 0.f; accS[r] = 0.f; }

    for (int j = 0; j < CHK; j++) {
        float ve = sv[j][e];
        float t1 = ve * cw[j];
        float t2 = ve * sw[j];
        #pragma unroll
        for (int r = 0; r < 16; r++) {
            float kd = sk[j][d0 + r];
            accC[r] = fmaf(kd, t1, accC[r]);
            accS[r] = fmaf(kd, t2, accS[r]);
        }
    }

    float* st = state + ((size_t)bh * NCH + c) * ST_STRIDE;
    #pragma unroll
    for (int r = 0; r < 16; r++) {
        st[(d0 + r) * 64 + e]        = accC[r];
        st[4096 + (d0 + r) * 64 + e] = accS[r];
    }
    if (tid < DD) {
        float zc = 0.f, zs = 0.f;
        for (int j = 0; j < CHK; j++) {
            float kd = sk[j][tid];
            zc = fmaf(kd, cw[j], zc);
            zs = fmaf(kd, sw[j], zs);
        }
        st[8192 + tid] = zc;
        st[8256 + tid] = zs;
    }
}

// ---------------------------------------------------------------------------
// Attention pass B: exclusive prefix over chunks (in-place).
// ---------------------------------------------------------------------------
__global__ void attn_prefix(float* __restrict__ state) {
    int bh  = blockIdx.y;
    int idx = blockIdx.x * 256 + threadIdx.x;
    if (idx >= ST_STRIDE) return;
    float* p = state + (size_t)bh * NCH * ST_STRIDE + idx;
    float vals[NCH];
    #pragma unroll
    for (int cc = 0; cc < NCH; cc++) vals[cc] = p[(size_t)cc * ST_STRIDE];
    float run = 0.f;
    #pragma unroll
    for (int cc = 0; cc < NCH; cc++) {
        p[(size_t)cc * ST_STRIDE] = run;
        run += vals[cc];
    }
}

// ---------------------------------------------------------------------------
// Attention pass C: per-chunk output.
// ---------------------------------------------------------------------------
#define ATTN_SMEM_FLOATS (6 * 64 * 65 + 64 + 64 + 64 + 64 + 256 + 64)
#define ATTN_SMEM_BYTES (ATTN_SMEM_FLOATS * 4)

__global__ void __launch_bounds__(256)
attn_out_kernel(const float* __restrict__ qkv, const float* __restrict__ state,
                float* __restrict__ out) {
    extern __shared__ float smf[];
    float* sq = smf;                // 64*65
    float* sk = sq + 4160;          // 64*65
    float* sv = sk + 4160;          // 64*65
    float* Sc = sv + 4160;          // 64*65
    float* Ss = Sc + 4160;          // 64*65
    float* AS = Ss + 4160;          // 64*65
    float* cw = AS + 4160;          // 64
    float* sw = cw + 64;            // 64
    float* Zc = sw + 64;            // 64
    float* Zs = Zc + 64;            // 64
    float* normp = Zs + 64;         // 4*64
    float* normF = normp + 256;     // 64

    int blk = blockIdx.x;
    int c = blk % NCH;
    int bh = blk / NCH;
    int b = bh / HH, h = bh % HH;
    int tid = threadIdx.x;

    const float* st = state + ((size_t)bh * NCH + c) * ST_STRIDE;

    for (int idx = tid; idx < CHK * 16; idx += 256) {
        int j = idx >> 4;
        int dd = (idx & 15) << 2;
        int l = c * CHK + j;
        const float* base = qkv + (size_t)(b * LL + l) * (3 * EE) + h * DD;
        float4 qv = *(const float4*)(base + dd);
        float4 kv = *(const float4*)(base + EE + dd);
        float4 vv = *(const float4*)(base + 2 * EE + dd);
        int ro = j * 65 + dd;
        sq[ro + 0] = fmaxf(qv.x, 0.f); sq[ro + 1] = fmaxf(qv.y, 0.f);
        sq[ro + 2] = fmaxf(qv.z, 0.f); sq[ro + 3] = fmaxf(qv.w, 0.f);
        sk[ro + 0] = fmaxf(kv.x, 0.f); sk[ro + 1] = fmaxf(kv.y, 0.f);
        sk[ro + 2] = fmaxf(kv.z, 0.f); sk[ro + 3] = fmaxf(kv.w, 0.f);
        sv[ro + 0] = vv.x; sv[ro + 1] = vv.y; sv[ro + 2] = vv.z; sv[ro + 3] = vv.w;
        int flat = idx << 2;
        int d = flat >> 6, e = flat & 63;
        float4 scv = *(const float4*)(st + flat);
        float4 ssv = *(const float4*)(st + 4096 + flat);
        int so = d * 65 + e;
        Sc[so + 0] = scv.x; Sc[so + 1] = scv.y; Sc[so + 2] = scv.z; Sc[so + 3] = scv.w;
        Ss[so + 0] = ssv.x; Ss[so + 1] = ssv.y; Ss[so + 2] = ssv.z; Ss[so + 3] = ssv.w;
    }
    if (tid < CHK) {
        float ang = 1.5707963267948966f * (float)(c * CHK + tid) / (float)LL;
        cw[tid] = cosf(ang);
        sw[tid] = sinf(ang);
        Zc[tid] = st[8192 + tid];
        Zs[tid] = st[8256 + tid];
    }
    __syncthreads();

    {
        int jc = tid >> 6;
        int i  = tid & 63;
        float acc[16];
        #pragma unroll
        for (int r = 0; r < 16; r++) acc[r] = 0.f;
        for (int d = 0; d < DD; d++) {
            float qv = sq[i * 65 + d];
            #pragma unroll
            for (int r = 0; r < 16; r++)
                acc[r] = fmaf(qv, sk[(jc * 16 + r) * 65 + d], acc[r]);
        }
        float cwi = cw[i], swi = sw[i];
        float rsum = 0.f;
        #pragma unroll
        for (int r = 0; r < 16; r++) {
            int j = jc * 16 + r;
            float wgt = (j <= i) ? (cwi * cw[j] + swi * sw[j]) : 0.f;
            float a = acc[r] * wgt;
            AS[i * 65 + j] = a;
            rsum += a;
        }
        normp[jc * 64 + i] = rsum;
    }
    __syncthreads();

    if (tid < 64) {
        int i = tid;
        float n = normp[i] + normp[64 + i] + normp[128 + i] + normp[192 + i];
        float dc = 0.f, ds = 0.f;
        for (int d = 0; d < DD; d++) {
            float qv = sq[i * 65 + d];
            dc = fmaf(qv, Zc[d], dc);
            ds = fmaf(qv, Zs[d], ds);
        }
        normF[i] = n + cw[i] * dc + sw[i] * ds;
    }

    int ec = tid >> 6;
    int i2 = tid & 63;
    int e0 = ec * 16;
    float accO[16], accC2[16], accS2[16];
    #pragma unroll
    for (int r = 0; r < 16; r++) { accO[r] = 0.f; accC2[r] = 0.f; accS2[r] = 0.f; }

    for (int j = 0; j < CHK; j++) {
        float av = AS[i2 * 65 + j];
        #pragma unroll
        for (int r = 0; r < 16; r++)
            accO[r] = fmaf(av, sv[j * 65 + e0 + r], accO[r]);
    }
    for (int d = 0; d < DD; d++) {
        float qv = sq[i2 * 65 + d];
        #pragma unroll
        for (int r = 0; r < 16; r++) {
            accC2[r] = fmaf(qv, Sc[d * 65 + e0 + r], accC2[r]);
            accS2[r] = fmaf(qv, Ss[d * 65 + e0 + r], accS2[r]);
        }
    }
    __syncthreads();

    float nrm = normF[i2] + 1e-6f;
    float inv = 1.0f / nrm;
    float cwi = cw[i2], swi = sw[i2];
    int lg = c * CHK + i2;
    float* op = out + (size_t)(b * LL + lg) * EE + h * DD + e0;
    #pragma unroll
    for (int r4 = 0; r4 < 4; r4++) {
        float4 o;
        o.x = (accO[r4*4+0] + cwi*accC2[r4*4+0] + swi*accS2[r4*4+0]) * inv;
        o.y = (accO[r4*4+1] + cwi*accC2[r4*4+1] + swi*accS2[r4*4+1]) * inv;
        o.z = (accO[r4*4+2] + cwi*accC2[r4*4+2] + swi*accS2[r4*4+2]) * inv;
        o.w = (accO[r4*4+3] + cwi*accC2[r4*4+3] + swi*accS2[r4*4+3]) * inv;
        *(float4*)(op + r4 * 4) = o;
    }
}

// ---------------------------------------------------------------------------
// launch
// ---------------------------------------------------------------------------
extern "C" void kernel_launch(void* const* d_in, const int* in_sizes, int n_in,
                              void* d_out, int out_size) {
    const float* x       = (const float*)d_in[0];
    const float* qkv_w   = (const float*)d_in[1];
    const float* qkv_b   = (const float*)d_in[2];
    const float* out_w   = (const float*)d_in[3];
    const float* out_b   = (const float*)d_in[4];
    const float* norm1_w = (const float*)d_in[5];
    const float* norm2_w = (const float*)d_in[6];
    const float* mlp_w1  = (const float*)d_in[7];
    const float* mlp_b1  = (const float*)d_in[8];
    const float* mlp_w2  = (const float*)d_in[9];
    const float* mlp_b2  = (const float*)d_in[10];
    float* out = (float*)d_out;

    float *xn, *qkv, *attn, *hbuf, *mid, *state;
    cudaGetSymbolAddress((void**)&xn, g_xn);
    cudaGetSymbolAddress((void**)&qkv, g_qkv);
    cudaGetSymbolAddress((void**)&attn, g_attn);
    cudaGetSymbolAddress((void**)&hbuf, g_h);
    cudaGetSymbolAddress((void**)&mid, g_mid);
    cudaGetSymbolAddress((void**)&state, g_state);

    cudaFuncSetAttribute(attn_out_kernel,
                         cudaFuncAttributeMaxDynamicSharedMemorySize,
                         ATTN_SMEM_BYTES);
    cudaFuncSetAttribute(tgemm_kernel,
                         cudaFuncAttributeMaxDynamicSharedMemorySize,
                         GEMM_SMEM_BYTES);

    // 1. xn = rmsnorm(x, norm1_w)
    rmsnorm_kernel<<<ROWS, 256>>>(x, norm1_w, xn);
    // 2. qkv = xn @ qkv_w + qkv_b
    tgemm_kernel<<<dim3(3 * EE / 128, ROWS / 128), 256, GEMM_SMEM_BYTES>>>(
        xn, qkv_w, qkv_b, nullptr, qkv, ROWS, 3 * EE, EE, 0);
    // 3-5. cosformer attention (chunked)
    attn_chunk_state<<<BB * HH * NCH, 256>>>(qkv, state);
    attn_prefix<<<dim3((ST_STRIDE + 255) / 256, BB * HH), 256>>>(state);
    attn_out_kernel<<<BB * HH * NCH, 256, ATTN_SMEM_BYTES>>>(qkv, state, attn);
    // 6. h = attn @ out_w + out_b + x
    tgemm_kernel<<<dim3(EE / 128, ROWS / 128), 256, GEMM_SMEM_BYTES>>>(
        attn, out_w, out_b, x, hbuf, ROWS, EE, EE, 2);
    // 7. xn = rmsnorm(h, norm2_w)
    rmsnorm_kernel<<<ROWS, 256>>>(hbuf, norm2_w, xn);
    // 8. mid = gelu(xn @ mlp_w1 + mlp_b1)
    tgemm_kernel<<<dim3(4 * EE / 128, ROWS / 128), 256, GEMM_SMEM_BYTES>>>(
        xn, mlp_w1, mlp_b1, nullptr, mid, ROWS, 4 * EE, EE, 1);
    // 9. out = mid @ mlp_w2 + mlp_b2 + h
    tgemm_kernel<<<dim3(EE / 128, ROWS / 128), 256, GEMM_SMEM_BYTES>>>(
        mid, mlp_w2, mlp_b2, hbuf, out, ROWS, EE, 4 * EE, 2);
}

// round 4
// speedup vs baseline: 1.2856x; 1.2856x over previous
#include <cuda_runtime.h>
#include <math.h>
#include <stdint.h>

// Problem constants
#define BB 2
#define LL 1024
#define EE 1024
#define HH 16
#define DD 64
#define NCH 16          // chunks per (b,h)
#define CHK 64          // chunk length
#define ST_STRIDE 8320  // per-chunk state: Sc(4096) Ss(4096) Zc(64) Zs(64)
#define ROWS (BB*LL)    // 2048

// GEMM smem config (tf32 bits), double buffered
#define APITCH 36       // A smem row pitch (words), layout [m][k]
#define BPITCH 136      // B smem row pitch (words), layout [k][n]
#define STAGE_WORDS (128 * APITCH + 32 * BPITCH)     // 4608 + 4352 = 8960
#define GEMM_SMEM_BYTES (2 * STAGE_WORDS * 4)        // 71680

// Scratch (device globals; no allocs allowed)
__device__ float g_xn[ROWS * EE];        // 8 MB
__device__ float g_qkv[ROWS * 3 * EE];   // 24 MB
__device__ float g_attn[ROWS * EE];      // 8 MB
__device__ float g_h[ROWS * EE];         // 8 MB
__device__ float g_mid[ROWS * 4 * EE];   // 32 MB
__device__ float g_state[BB * HH * NCH * ST_STRIDE]; // ~17 MB

// ---------------------------------------------------------------------------
// RMSNorm: one block per row (E=1024), 256 threads, 1 float4 each
// ---------------------------------------------------------------------------
__global__ void rmsnorm_kernel(const float* __restrict__ x,
                               const float* __restrict__ w,
                               float* __restrict__ out) {
    int row = blockIdx.x;
    int tid = threadIdx.x;
    const float4* xr = (const float4*)(x + (size_t)row * EE);
    float4 v = xr[tid];
    float ss = v.x*v.x + v.y*v.y + v.z*v.z + v.w*v.w;
    #pragma unroll
    for (int o = 16; o; o >>= 1) ss += __shfl_xor_sync(0xffffffffu, ss, o);
    __shared__ float red[8];
    if ((tid & 31) == 0) red[tid >> 5] = ss;
    __syncthreads();
    float tot = 0.f;
    #pragma unroll
    for (int i = 0; i < 8; i++) tot += red[i];
    float scale = rsqrtf(tot * (1.0f / (float)EE) + 1e-6f);
    float4 wv = ((const float4*)w)[tid];
    float4 o;
    o.x = v.x * scale * wv.x;
    o.y = v.y * scale * wv.y;
    o.z = v.z * scale * wv.z;
    o.w = v.w * scale * wv.w;
    ((float4*)(out + (size_t)row * EE))[tid] = o;
}

// ---------------------------------------------------------------------------
// TF32 tensor-core GEMM, issue-optimized:
//  - tf32 conversion at smem-store time (amortized)
//  - A fragments via ldmatrix.m8n8.x4 (b32 reinterp of b16), conflict-free
//  - B fragments via conflict-free scalar LDS (pitch 136)
//  - double-buffered smem, register-staged global prefetch, 1 sync/tile
// C[M,N] = A[M,K] @ W[K,N] + bias (+GELU | +residual)
// 128x128 tile, BK=32, 256 threads = 8 warps (2x4), warp tile 64x32.
// epi: 0 = bias, 1 = bias+gelu(tanh), 2 = bias+residual
// ---------------------------------------------------------------------------
__device__ __forceinline__ uint32_t f2tf32(float f) {
    uint32_t r;
    asm("cvt.rna.tf32.f32 %0, %1;" : "=r"(r) : "f"(f));
    return r;
}

__device__ __forceinline__ void mma_tf32(float* c, const uint32_t* a, const uint32_t* b) {
    asm volatile(
        "mma.sync.aligned.m16n8k8.row.col.f32.tf32.tf32.f32 "
        "{%0,%1,%2,%3}, {%4,%5,%6,%7}, {%8,%9}, {%0,%1,%2,%3};"
        : "+f"(c[0]), "+f"(c[1]), "+f"(c[2]), "+f"(c[3])
        : "r"(a[0]), "r"(a[1]), "r"(a[2]), "r"(a[3]),
          "r"(b[0]), "r"(b[1]));
}

__device__ __forceinline__ void ldsm_x4(uint32_t* d, uint32_t saddr) {
    asm volatile("ldmatrix.sync.aligned.m8n8.x4.shared.b16 {%0,%1,%2,%3}, [%4];"
                 : "=r"(d[0]), "=r"(d[1]), "=r"(d[2]), "=r"(d[3])
                 : "r"(saddr));
}

__global__ void __launch_bounds__(256)
tgemm_kernel(const float* __restrict__ A, const float* __restrict__ W,
             const float* __restrict__ bias, const float* __restrict__ res,
             float* __restrict__ C, int M, int N, int K, int epi) {
    extern __shared__ uint32_t smu[];

    int tid = threadIdx.x;
    int bx = blockIdx.x;   // N tile
    int by = blockIdx.y;   // M tile
    int warp = tid >> 5;
    int lane = tid & 31;
    int wm = warp >> 2;    // 0..1  (M dir, 64 rows each)
    int wn = warp & 3;     // 0..3  (N dir, 32 cols each)
    int g  = lane >> 2;    // 0..7
    int tg = lane & 3;     // 0..3

    float acc[4][4][4];
    #pragma unroll
    for (int mi = 0; mi < 4; mi++)
        #pragma unroll
        for (int ni = 0; ni < 4; ni++)
            #pragma unroll
            for (int r = 0; r < 4; r++) acc[mi][ni][r] = 0.f;

    // -- global load / smem store mappings --
    // A: thread -> row m = tid>>1, k base = (tid&1)*16; 4 x float4
    int am = tid >> 1;
    int ak = (tid & 1) * 16;
    const float* Ag = A + (size_t)(by * 128 + am) * K + ak;
    // B: thread -> row k = tid>>3, n base = (tid&7)*4; 4 x float4 at n+32*i
    int bk = tid >> 3;
    int bn = (tid & 7) * 4;
    const float* Wg = W + (size_t)bk * N + bx * 128 + bn;

    // ldmatrix per-lane row offset for A fragments
    int sel = lane >> 3;       // 0..3: (m-half, k-half)
    int rr  = lane & 7;
    int aLaneOff = ((sel & 1) * 8 + rr) * APITCH + (sel >> 1) * 4;

    int m0base = wm * 64;
    int n0base = wn * 32;

    int nT = K >> 5;
    float4 aReg[4], bReg[4];

    auto ldg = [&](int t) {
        const float* Asrc = Ag + t * 32;
        const float* Bsrc = Wg + (size_t)t * 32 * N;
        #pragma unroll
        for (int i = 0; i < 4; i++) aReg[i] = *(const float4*)(Asrc + i * 4);
        #pragma unroll
        for (int i = 0; i < 4; i++) bReg[i] = *(const float4*)(Bsrc + i * 32);
    };
    auto sts = [&](int buf) {
        uint32_t* sA = smu + buf * STAGE_WORDS;
        uint32_t* sB = sA + 128 * APITCH;
        #pragma unroll
        for (int i = 0; i < 4; i++) {
            uint4 u;
            u.x = f2tf32(aReg[i].x); u.y = f2tf32(aReg[i].y);
            u.z = f2tf32(aReg[i].z); u.w = f2tf32(aReg[i].w);
            *(uint4*)&sA[am * APITCH + ak + i * 4] = u;
        }
        #pragma unroll
        for (int i = 0; i < 4; i++) {
            uint4 u;
            u.x = f2tf32(bReg[i].x); u.y = f2tf32(bReg[i].y);
            u.z = f2tf32(bReg[i].z); u.w = f2tf32(bReg[i].w);
            *(uint4*)&sB[bk * BPITCH + bn + i * 32] = u;
        }
    };

    // prologue: tile 0 -> buf0; prefetch tile 1 into regs
    ldg(0);
    sts(0);
    ldg(1);
    __syncthreads();

    for (int t = 0; t < nT; t++) {
        // stage tile t+1 into the other buffer; prefetch t+2
        if (t + 1 < nT) sts((t + 1) & 1);
        if (t + 2 < nT) ldg(t + 2);

        uint32_t* sA = smu + (t & 1) * STAGE_WORDS;
        uint32_t* sB = sA + 128 * APITCH;
        uint32_t sAaddr = (uint32_t)__cvta_generic_to_shared(sA);

        #pragma unroll
        for (int ks = 0; ks < 4; ks++) {
            int k0 = ks * 8;
            uint32_t af[4][4];
            #pragma unroll
            for (int mi = 0; mi < 4; mi++) {
                uint32_t addr = sAaddr +
                    4u * (uint32_t)((m0base + mi * 16) * APITCH + k0 + aLaneOff);
                ldsm_x4(af[mi], addr);
            }
            uint32_t bf[4][2];
            #pragma unroll
            for (int ni = 0; ni < 4; ni++) {
                int idx = (k0 + tg) * BPITCH + n0base + ni * 8 + g;
                bf[ni][0] = sB[idx];
                bf[ni][1] = sB[idx + 4 * BPITCH];
            }
            #pragma unroll
            for (int mi = 0; mi < 4; mi++)
                #pragma unroll
                for (int ni = 0; ni < 4; ni++)
                    mma_tf32(acc[mi][ni], af[mi], bf[ni]);
        }
        __syncthreads();
    }

    // Epilogue. c0:(g, 2tg) c1:(g, 2tg+1) c2:(g+8, 2tg) c3:(g+8, 2tg+1)
    #pragma unroll
    for (int mi = 0; mi < 4; mi++) {
        #pragma unroll
        for (int ni = 0; ni < 4; ni++) {
            int col = bx * 128 + wn * 32 + ni * 8 + tg * 2;
            float b0 = bias[col], b1 = bias[col + 1];
            #pragma unroll
            for (int half = 0; half < 2; half++) {
                int row = by * 128 + wm * 64 + mi * 16 + g + half * 8;
                size_t off = (size_t)row * N + col;
                float v0 = acc[mi][ni][half * 2 + 0] + b0;
                float v1 = acc[mi][ni][half * 2 + 1] + b1;
                if (epi == 1) {
                    float u0 = v0 * (0.7978845608028654f + 0.035677408136300125f * v0 * v0);
                    float u1 = v1 * (0.7978845608028654f + 0.035677408136300125f * v1 * v1);
                    v0 = 0.5f * v0 * (1.f + tanhf(u0));
                    v1 = 0.5f * v1 * (1.f + tanhf(u1));
                } else if (epi == 2) {
                    v0 += res[off];
                    v1 += res[off + 1];
                }
                *(float2*)(C + off) = make_float2(v0, v1);
            }
        }
    }
}

// ---------------------------------------------------------------------------
// Attention pass A: per-chunk state sums.
// ---------------------------------------------------------------------------
__global__ void __launch_bounds__(256)
attn_chunk_state(const float* __restrict__ qkv, float* __restrict__ state) {
    int blk = blockIdx.x;
    int c = blk % NCH;
    int bh = blk / NCH;
    int b = bh / HH, h = bh % HH;

    __shared__ float sk[CHK][DD + 1];
    __shared__ float sv[CHK][DD + 1];
    __shared__ float cw[CHK], sw[CHK];

    int tid = threadIdx.x;
    for (int idx = tid; idx < CHK * 16; idx += 256) {
        int j = idx >> 4;
        int dd = (idx & 15) << 2;
        int l = c * CHK + j;
        const float* base = qkv + (size_t)(b * LL + l) * (3 * EE) + h * DD;
        float4 kv = *(const float4*)(base + EE + dd);
        float4 vv = *(const float4*)(base + 2 * EE + dd);
        sk[j][dd + 0] = fmaxf(kv.x, 0.f);
        sk[j][dd + 1] = fmaxf(kv.y, 0.f);
        sk[j][dd + 2] = fmaxf(kv.z, 0.f);
        sk[j][dd + 3] = fmaxf(kv.w, 0.f);
        sv[j][dd + 0] = vv.x;
        sv[j][dd + 1] = vv.y;
        sv[j][dd + 2] = vv.z;
        sv[j][dd + 3] = vv.w;
    }
    if (tid < CHK) {
        float ang = 1.5707963267948966f * (float)(c * CHK + tid) / (float)LL;
        cw[tid] = cosf(ang);
        sw[tid] = sinf(ang);
    }
    __syncthreads();

    int e  = tid & 63;
    int d0 = (tid >> 6) * 16;
    float accC[16], accS[16];
    #pragma unroll
    for (int r = 0; r < 16; r++) { accC[r] = 0.f; accS[r] = 0.f; }

    for (int j = 0; j < CHK; j++) {
        float ve = sv[j][e];
        float t1 = ve * cw[j];
        float t2 = ve * sw[j];
        #pragma unroll
        for (int r = 0; r < 16; r++) {
            float kd = sk[j][d0 + r];
            accC[r] = fmaf(kd, t1, accC[r]);
            accS[r] = fmaf(kd, t2, accS[r]);
        }
    }

    float* st = state + ((size_t)bh * NCH + c) * ST_STRIDE;
    #pragma unroll
    for (int r = 0; r < 16; r++) {
        st[(d0 + r) * 64 + e]        = accC[r];
        st[4096 + (d0 + r) * 64 + e] = accS[r];
    }
    if (tid < DD) {
        float zc = 0.f, zs = 0.f;
        for (int j = 0; j < CHK; j++) {
            float kd = sk[j][tid];
            zc = fmaf(kd, cw[j], zc);
            zs = fmaf(kd, sw[j], zs);
        }
        st[8192 + tid] = zc;
        st[8256 + tid] = zs;
    }
}

// ---------------------------------------------------------------------------
// Attention pass B: exclusive prefix over chunks (in-place).
// ---------------------------------------------------------------------------
__global__ void attn_prefix(float* __restrict__ state) {
    int bh  = blockIdx.y;
    int idx = blockIdx.x * 256 + threadIdx.x;
    if (idx >= ST_STRIDE) return;
    float* p = state + (size_t)bh * NCH * ST_STRIDE + idx;
    float vals[NCH];
    #pragma unroll
    for (int cc = 0; cc < NCH; cc++) vals[cc] = p[(size_t)cc * ST_STRIDE];
    float run = 0.f;
    #pragma unroll
    for (int cc = 0; cc < NCH; cc++) {
        p[(size_t)cc * ST_STRIDE] = run;
        run += vals[cc];
    }
}

// ---------------------------------------------------------------------------
// Attention pass C: per-chunk output.
// ---------------------------------------------------------------------------
#define ATTN_SMEM_FLOATS (6 * 64 * 65 + 64 + 64 + 64 + 64 + 256 + 64)
#define ATTN_SMEM_BYTES (ATTN_SMEM_FLOATS * 4)

__global__ void __launch_bounds__(256)
attn_out_kernel(const float* __restrict__ qkv, const float* __restrict__ state,
                float* __restrict__ out) {
    extern __shared__ float smf[];
    float* sq = smf;                // 64*65
    float* sk = sq + 4160;          // 64*65
    float* sv = sk + 4160;          // 64*65
    float* Sc = sv + 4160;          // 64*65
    float* Ss = Sc + 4160;          // 64*65
    float* AS = Ss + 4160;          // 64*65
    float* cw = AS + 4160;          // 64
    float* sw = cw + 64;            // 64
    float* Zc = sw + 64;            // 64
    float* Zs = Zc + 64;            // 64
    float* normp = Zs + 64;         // 4*64
    float* normF = normp + 256;     // 64

    int blk = blockIdx.x;
    int c = blk % NCH;
    int bh = blk / NCH;
    int b = bh / HH, h = bh % HH;
    int tid = threadIdx.x;

    const float* st = state + ((size_t)bh * NCH + c) * ST_STRIDE;

    for (int idx = tid; idx < CHK * 16; idx += 256) {
        int j = idx >> 4;
        int dd = (idx & 15) << 2;
        int l = c * CHK + j;
        const float* base = qkv + (size_t)(b * LL + l) * (3 * EE) + h * DD;
        float4 qv = *(const float4*)(base + dd);
        float4 kv = *(const float4*)(base + EE + dd);
        float4 vv = *(const float4*)(base + 2 * EE + dd);
        int ro = j * 65 + dd;
        sq[ro + 0] = fmaxf(qv.x, 0.f); sq[ro + 1] = fmaxf(qv.y, 0.f);
        sq[ro + 2] = fmaxf(qv.z, 0.f); sq[ro + 3] = fmaxf(qv.w, 0.f);
        sk[ro + 0] = fmaxf(kv.x, 0.f); sk[ro + 1] = fmaxf(kv.y, 0.f);
        sk[ro + 2] = fmaxf(kv.z, 0.f); sk[ro + 3] = fmaxf(kv.w, 0.f);
        sv[ro + 0] = vv.x; sv[ro + 1] = vv.y; sv[ro + 2] = vv.z; sv[ro + 3] = vv.w;
        int flat = idx << 2;
        int d = flat >> 6, e = flat & 63;
        float4 scv = *(const float4*)(st + flat);
        float4 ssv = *(const float4*)(st + 4096 + flat);
        int so = d * 65 + e;
        Sc[so + 0] = scv.x; Sc[so + 1] = scv.y; Sc[so + 2] = scv.z; Sc[so + 3] = scv.w;
        Ss[so + 0] = ssv.x; Ss[so + 1] = ssv.y; Ss[so + 2] = ssv.z; Ss[so + 3] = ssv.w;
    }
    if (tid < CHK) {
        float ang = 1.5707963267948966f * (float)(c * CHK + tid) / (float)LL;
        cw[tid] = cosf(ang);
        sw[tid] = sinf(ang);
        Zc[tid] = st[8192 + tid];
        Zs[tid] = st[8256 + tid];
    }
    __syncthreads();

    {
        int jc = tid >> 6;
        int i  = tid & 63;
        float acc[16];
        #pragma unroll
        for (int r = 0; r < 16; r++) acc[r] = 0.f;
        for (int d = 0; d < DD; d++) {
            float qv = sq[i * 65 + d];
            #pragma unroll
            for (int r = 0; r < 16; r++)
                acc[r] = fmaf(qv, sk[(jc * 16 + r) * 65 + d], acc[r]);
        }
        float cwi = cw[i], swi = sw[i];
        float rsum = 0.f;
        #pragma unroll
        for (int r = 0; r < 16; r++) {
            int j = jc * 16 + r;
            float wgt = (j <= i) ? (cwi * cw[j] + swi * sw[j]) : 0.f;
            float a = acc[r] * wgt;
            AS[i * 65 + j] = a;
            rsum += a;
        }
        normp[jc * 64 + i] = rsum;
    }
    __syncthreads();

    if (tid < 64) {
        int i = tid;
        float n = normp[i] + normp[64 + i] + normp[128 + i] + normp[192 + i];
        float dc = 0.f, ds = 0.f;
        for (int d = 0; d < DD; d++) {
            float qv = sq[i * 65 + d];
            dc = fmaf(qv, Zc[d], dc);
            ds = fmaf(qv, Zs[d], ds);
        }
        normF[i] = n + cw[i] * dc + sw[i] * ds;
    }

    int ec = tid >> 6;
    int i2 = tid & 63;
    int e0 = ec * 16;
    float accO[16], accC2[16], accS2[16];
    #pragma unroll
    for (int r = 0; r < 16; r++) { accO[r] = 0.f; accC2[r] = 0.f; accS2[r] = 0.f; }

    for (int j = 0; j < CHK; j++) {
        float av = AS[i2 * 65 + j];
        #pragma unroll
        for (int r = 0; r < 16; r++)
            accO[r] = fmaf(av, sv[j * 65 + e0 + r], accO[r]);
    }
    for (int d = 0; d < DD; d++) {
        float qv = sq[i2 * 65 + d];
        #pragma unroll
        for (int r = 0; r < 16; r++) {
            accC2[r] = fmaf(qv, Sc[d * 65 + e0 + r], accC2[r]);
            accS2[r] = fmaf(qv, Ss[d * 65 + e0 + r], accS2[r]);
        }
    }
    __syncthreads();

    float nrm = normF[i2] + 1e-6f;
    float inv = 1.0f / nrm;
    float cwi = cw[i2], swi = sw[i2];
    int lg = c * CHK + i2;
    float* op = out + (size_t)(b * LL + lg) * EE + h * DD + e0;
    #pragma unroll
    for (int r4 = 0; r4 < 4; r4++) {
        float4 o;
        o.x = (accO[r4*4+0] + cwi*accC2[r4*4+0] + swi*accS2[r4*4+0]) * inv;
        o.y = (accO[r4*4+1] + cwi*accC2[r4*4+1] + swi*accS2[r4*4+1]) * inv;
        o.z = (accO[r4*4+2] + cwi*accC2[r4*4+2] + swi*accS2[r4*4+2]) * inv;
        o.w = (accO[r4*4+3] + cwi*accC2[r4*4+3] + swi*accS2[r4*4+3]) * inv;
        *(float4*)(op + r4 * 4) = o;
    }
}

// ---------------------------------------------------------------------------
// launch
// ---------------------------------------------------------------------------
extern "C" void kernel_launch(void* const* d_in, const int* in_sizes, int n_in,
                              void* d_out, int out_size) {
    const float* x       = (const float*)d_in[0];
    const float* qkv_w   = (const float*)d_in[1];
    const float* qkv_b   = (const float*)d_in[2];
    const float* out_w   = (const float*)d_in[3];
    const float* out_b   = (const float*)d_in[4];
    const float* norm1_w = (const float*)d_in[5];
    const float* norm2_w = (const float*)d_in[6];
    const float* mlp_w1  = (const float*)d_in[7];
    const float* mlp_b1  = (const float*)d_in[8];
    const float* mlp_w2  = (const float*)d_in[9];
    const float* mlp_b2  = (const float*)d_in[10];
    float* out = (float*)d_out;

    float *xn, *qkv, *attn, *hbuf, *mid, *state;
    cudaGetSymbolAddress((void**)&xn, g_xn);
    cudaGetSymbolAddress((void**)&qkv, g_qkv);
    cudaGetSymbolAddress((void**)&attn, g_attn);
    cudaGetSymbolAddress((void**)&hbuf, g_h);
    cudaGetSymbolAddress((void**)&mid, g_mid);
    cudaGetSymbolAddress((void**)&state, g_state);

    cudaFuncSetAttribute(attn_out_kernel,
                         cudaFuncAttributeMaxDynamicSharedMemorySize,
                         ATTN_SMEM_BYTES);
    cudaFuncSetAttribute(tgemm_kernel,
                         cudaFuncAttributeMaxDynamicSharedMemorySize,
                         GEMM_SMEM_BYTES);

    // 1. xn = rmsnorm(x, norm1_w)
    rmsnorm_kernel<<<ROWS, 256>>>(x, norm1_w, xn);
    // 2. qkv = xn @ qkv_w + qkv_b
    tgemm_kernel<<<dim3(3 * EE / 128, ROWS / 128), 256, GEMM_SMEM_BYTES>>>(
        xn, qkv_w, qkv_b, nullptr, qkv, ROWS, 3 * EE, EE, 0);
    // 3-5. cosformer attention (chunked)
    attn_chunk_state<<<BB * HH * NCH, 256>>>(qkv, state);
    attn_prefix<<<dim3((ST_STRIDE + 255) / 256, BB * HH), 256>>>(state);
    attn_out_kernel<<<BB * HH * NCH, 256, ATTN_SMEM_BYTES>>>(qkv, state, attn);
    // 6. h = attn @ out_w + out_b + x
    tgemm_kernel<<<dim3(EE / 128, ROWS / 128), 256, GEMM_SMEM_BYTES>>>(
        attn, out_w, out_b, x, hbuf, ROWS, EE, EE, 2);
    // 7. xn = rmsnorm(h, norm2_w)
    rmsnorm_kernel<<<ROWS, 256>>>(hbuf, norm2_w, xn);
    // 8. mid = gelu(xn @ mlp_w1 + mlp_b1)
    tgemm_kernel<<<dim3(4 * EE / 128, ROWS / 128), 256, GEMM_SMEM_BYTES>>>(
        xn, mlp_w1, mlp_b1, nullptr, mid, ROWS, 4 * EE, EE, 1);
    // 9. out = mid @ mlp_w2 + mlp_b2 + h
    tgemm_kernel<<<dim3(EE / 128, ROWS / 128), 256, GEMM_SMEM_BYTES>>>(
        mid, mlp_w2, mlp_b2, hbuf, out, ROWS, EE, 4 * EE, 2);
}